// round 15
// baseline (speedup 1.0000x reference)
#include <cuda_runtime.h>

// CFConv: y[i] = sum_{e: idx_i[e]==i} x[idx_j[e]] * Wij[e]
// x:[50000,64] f32, Wij:[E=1.25M,64] f32, idx_i sorted.
//
// R15: R14's pair-stage cp.async ring unchanged, resource envelope retuned:
// DS 4->3 (12KB smem/block) + __launch_bounds__(64,18) => 18 blocks/SM,
// 36 resident warps (was 28). Pure occupancy experiment at the lean
// ~15-instr/edge loop. Half-warp float4 lanes; sorted-segment register
// accumulation; plain stores for interior segments; red.global.add.v4.f32
// at task boundaries.

#define FEAT   64
#define F4     (FEAT / 4)      // 16 float4 per feature row
#define HALF   64              // edges per half-warp task
#define CHUNK  (2 * HALF)      // edges per warp
#define S      (HALF / 2)      // 32 pairs per task
#define DS     3               // ring depth in pairs (6 edges in flight)
#define WPB    2               // warps per block
#define TPB    (WPB * 32)

#define CP_COMMIT()  asm volatile("cp.async.commit_group;" ::: "memory")

template <int N>
__device__ __forceinline__ void cp_wait() {
    asm volatile("cp.async.wait_group %0;" :: "n"(N) : "memory");
}

__device__ __forceinline__ void red_add_f4(float* p, float4 v) {
    asm volatile("red.global.add.v4.f32 [%0], {%1,%2,%3,%4};"
                 :: "l"(p), "f"(v.x), "f"(v.y), "f"(v.z), "f"(v.w)
                 : "memory");
}

__device__ __forceinline__ void fma4(float4& a, float4 x, float4 w) {
    a.x = fmaf(x.x, w.x, a.x);
    a.y = fmaf(x.y, w.y, a.y);
    a.z = fmaf(x.z, w.z, a.z);
    a.w = fmaf(x.w, w.w, a.w);
}

__device__ __forceinline__ void flush(float* __restrict__ y, int seg, int fl,
                                      float4 acc, bool& first)
{
    float* dst = y + (size_t)seg * FEAT + fl * 4;
    if (first) { red_add_f4(dst, acc); first = false; }
    else       { *reinterpret_cast<float4*>(dst) = acc; }  // exclusive interior
}

__device__ __forceinline__ void cp16(void* smem_dst, const void* gmem_src) {
    unsigned           ds = (unsigned)__cvta_generic_to_shared(smem_dst);
    unsigned long long gs = (unsigned long long)__cvta_generic_to_global(gmem_src);
    asm volatile("cp.async.cg.shared.global [%0], [%1], 16;"
                 :: "r"(ds), "l"(gs) : "memory");
}

// consume one edge: segment bookkeeping + fma
__device__ __forceinline__ void consume(
    float* __restrict__ y, int fl, int ei, float4 xv, float4 wv,
    int& prev, bool& first, float4& acc)
{
    if (ei != prev) {
        flush(y, prev, fl, acc, first);
        acc  = make_float4(0.f, 0.f, 0.f, 0.f);
        prev = ei;
    }
    fma4(acc, xv, wv);
}

// Phase 2: consume the last DS pairs; wait counts/clamps are compile-time.
template <int ST, int M>
__device__ __forceinline__ void phase2(
    const float4 (&sW)[WPB][DS][2][32], const float4 (&sX)[WPB][DS][2][32],
    const int* __restrict__ ii, float* __restrict__ y,
    int w, int lane, int fl, long long s,
    int& ci, int& prev, bool& first, float4& acc)
{
    if constexpr (M < DS) {
        constexpr int k  = S - DS + M;           // pair index
        constexpr int st = k % DS;
        cp_wait<DS - 1 - M>();
        float4 wv0 = sW[w][st][0][lane];
        float4 xv0 = sX[w][st][0][lane];
        float4 wv1 = sW[w][st][1][lane];
        float4 xv1 = sX[w][st][1][lane];

        constexpr int e1 = 2 * k + 1;                          // <= 63
        constexpr int e2 = (2 * k + 2 > HALF - 1) ? (HALF - 1) : (2 * k + 2);
        int ci1 = ii[(s + e1) * ST];
        int ci2 = ii[(s + e2) * ST];

        consume(y, fl, ci,  xv0, wv0, prev, first, acc);
        consume(y, fl, ci1, xv1, wv1, prev, first, acc);
        ci = ci2;

        phase2<ST, M + 1>(sW, sX, ii, y, w, lane, fl, s, ci, prev, first, acc);
    }
}

// ST = index element stride in int32 words (1 = int32, 2 = LE int64 with
// values < 2^31 -> read the low word).
template <int ST>
__device__ __forceinline__ void cfconv_body(
    const float4* __restrict__ X4, const float4* __restrict__ W4,
    const int* __restrict__ ii, const int* __restrict__ jj,
    float* __restrict__ y,
    float4 (&sW)[WPB][DS][2][32], float4 (&sX)[WPB][DS][2][32],
    int w, int lane, int fl, long long s, int cnt)
{
    const float4* wp = W4 + (size_t)s * F4 + fl;

    int    prev;
    bool   first = true;               // first segment may start before s
    float4 acc   = make_float4(0.f, 0.f, 0.f, 0.f);

    if (cnt == HALF) {
        // -------- pair-stage pipelined path --------
        // prologue: fill DS stages (one commit group per stage, 2 edges each)
        #pragma unroll
        for (int d = 0; d < DS; ++d) {
            int j0 = jj[(s + 2 * d)     * ST];
            int j1 = jj[(s + 2 * d + 1) * ST];
            cp16(&sW[w][d][0][lane], wp + (size_t)(2 * d)     * F4);
            cp16(&sW[w][d][1][lane], wp + (size_t)(2 * d + 1) * F4);
            cp16(&sX[w][d][0][lane], X4 + (size_t)j0 * F4 + fl);
            cp16(&sX[w][d][1][lane], X4 + (size_t)j1 * F4 + fl);
            CP_COMMIT();
        }
        int ci = ii[s * ST];
        prev = ci;

        // ---- phase 1: pairs 0..S-DS-1 — no guards, no clamps
        #pragma unroll 1
        for (int k = 0; k < S - DS; ++k) {
            cp_wait<DS - 1>();
            int st = k % DS;
            float4 wv0 = sW[w][st][0][lane];
            float4 xv0 = sX[w][st][0][lane];
            float4 wv1 = sW[w][st][1][lane];
            float4 xv1 = sX[w][st][1][lane];

            // prefetch pair k+DS (edges 2k+6, 2k+7 <= 63: always in-task)
            int e  = 2 * (k + DS);
            int j0 = jj[(s + e)     * ST];
            int j1 = jj[(s + e + 1) * ST];
            cp16(&sW[w][st][0][lane], wp + (size_t)e       * F4);
            cp16(&sW[w][st][1][lane], wp + (size_t)(e + 1) * F4);
            cp16(&sX[w][st][0][lane], X4 + (size_t)j0 * F4 + fl);
            cp16(&sX[w][st][1][lane], X4 + (size_t)j1 * F4 + fl);
            CP_COMMIT();

            // idx for this pair's 2nd edge and next pair's 1st (in-task)
            int ci1 = ii[(s + 2 * k + 1) * ST];
            int ci2 = ii[(s + 2 * k + 2) * ST];

            consume(y, fl, ci,  xv0, wv0, prev, first, acc);
            consume(y, fl, ci1, xv1, wv1, prev, first, acc);
            ci = ci2;
        }

        // ---- phase 2: last DS pairs — constant wait counts, no prefetch
        phase2<ST, 0>(sW, sX, ii, y, w, lane, fl, s, ci, prev, first, acc);
    } else {
        // -------- scalar tail path (at most one partial task) --------
        int    ic = ii[s * ST];
        int    jc = jj[s * ST];
        float4 wc = __ldcs(wp);
        float4 xc = X4[(size_t)jc * F4 + fl];
        prev = ic;
        for (int k = 1; k < cnt; ++k) {
            int    in_ = ii[(s + k) * ST];
            int    jn  = jj[(s + k) * ST];
            float4 wn  = __ldcs(wp + (size_t)k * F4);
            float4 xn  = X4[(size_t)jn * F4 + fl];
            consume(y, fl, ic, xc, wc, prev, first, acc);
            ic = in_; wc = wn; xc = xn;
        }
        consume(y, fl, ic, xc, wc, prev, first, acc);
    }

    // final segment may extend into the next task -> atomic
    red_add_f4(y + (size_t)prev * FEAT + fl * 4, acc);
}

__global__ __launch_bounds__(TPB, 18) void cfconv_kernel(
    const float4* __restrict__ X4, const float4* __restrict__ W4,
    const void* __restrict__ ii_p, const void* __restrict__ jj_p,
    float* __restrict__ y, int E)
{
    __shared__ float4 sW[WPB][DS][2][32];
    __shared__ float4 sX[WPB][DS][2][32];

    int tid  = threadIdx.x;
    int w    = tid >> 5;
    int lane = tid & 31;
    int half = lane >> 4;
    int fl   = lane & 15;

    int gwarp = blockIdx.x * WPB + w;
    long long base = (long long)gwarp * CHUNK;
    if (base >= E) return;
    long long s = base + (long long)half * HALF;
    if (s >= E) return;
    long long se = s + HALF; if (se > E) se = E;
    int cnt = (int)(se - s);

    // dtype probe (uniform): LE int64 -> int32 word at odd position (E/2)|1 is
    // a zero high word; int32 -> sorted idx_i median ~N/2 != 0.
    int probe = reinterpret_cast<const int*>(ii_p)[(E / 2) | 1];
    const int* ii = reinterpret_cast<const int*>(ii_p);
    const int* jj = reinterpret_cast<const int*>(jj_p);
    if (probe == 0) {
        cfconv_body<2>(X4, W4, ii, jj, y, sW, sX, w, lane, fl, s, cnt);
    } else {
        cfconv_body<1>(X4, W4, ii, jj, y, sW, sX, w, lane, fl, s, cnt);
    }
}

extern "C" void kernel_launch(void* const* d_in, const int* in_sizes, int n_in,
                              void* d_out, int out_size)
{
    const float* x   = (const float*)d_in[0];   // [N, 64]
    const float* Wij = (const float*)d_in[1];   // [E, 64]
    const void*  ii  = d_in[2];                 // [E] int64 or int32
    const void*  jj  = d_in[3];                 // [E] int64 or int32
    float*       y   = (float*)d_out;           // [N, 64]

    int E = in_sizes[1] / FEAT;

    // zero output (memset node — graph-capturable)
    cudaMemsetAsync(d_out, 0, (size_t)out_size * sizeof(float), 0);

    int nwarps  = (E + CHUNK - 1) / CHUNK;
    int nblocks = (nwarps + WPB - 1) / WPB;
    cfconv_kernel<<<nblocks, TPB>>>((const float4*)x, (const float4*)Wij,
                                    ii, jj, y, E);
}